// round 2
// baseline (speedup 1.0000x reference)
#include <cuda_runtime.h>
#include <cuda_bf16.h>
#include <cstddef>

#define NN 100000
#define EE 3200000

// ---------------- scratch (static device allocations; no cudaMalloc) ----------
__device__ float g_H[NN * 32];        // neighbor-transformed features (x @ Wn)
__device__ float g_S[NN * 32];        // self part (x @ Ws + bn)
__device__ float g_L[3][NN * 32];     // per-layer outputs (kept for concat)
__device__ int   g_deg[NN];
__device__ int   g_cursor[NN];
__device__ int   g_rowptr[NN + 1];
__device__ int   g_csrc[EE];          // CSR-by-dst: source node ids

// ---------------- CSR build --------------------------------------------------
__global__ void zero_deg_k() {
    int i = blockIdx.x * blockDim.x + threadIdx.x;
    if (i < NN) g_deg[i] = 0;
}

__global__ void count_k(const int* __restrict__ dst) {
    int e = blockIdx.x * blockDim.x + threadIdx.x;
    if (e < EE) atomicAdd(&g_deg[dst[e]], 1);
}

// Single-block exclusive scan over g_deg -> g_rowptr (+ cursor copy).
__global__ void scan_k() {
    const int T = 1024;
    const int chunk = (NN + T - 1) / T;   // 98
    int t = threadIdx.x;
    int start = t * chunk;
    int end = start + chunk;
    if (end > NN) end = NN;

    int s = 0;
    for (int i = start; i < end; i++) s += g_deg[i];

    __shared__ int sums[T];
    sums[t] = s;
    __syncthreads();
    // Hillis-Steele inclusive scan
    for (int off = 1; off < T; off <<= 1) {
        int v = (t >= off) ? sums[t - off] : 0;
        __syncthreads();
        sums[t] += v;
        __syncthreads();
    }
    int run = (t == 0) ? 0 : sums[t - 1];
    for (int i = start; i < end; i++) {
        g_rowptr[i] = run;
        g_cursor[i] = run;
        run += g_deg[i];
    }
    if (start < NN && end == NN) g_rowptr[NN] = run;
}

__global__ void fill_k(const int* __restrict__ src, const int* __restrict__ dst) {
    int e = blockIdx.x * blockDim.x + threadIdx.x;
    if (e < EE) {
        int p = atomicAdd(&g_cursor[dst[e]], 1);
        g_csrc[p] = src[e];
    }
}

// ---------------- per-layer GEMM: H = X@Wn ; S = X@Ws + bn -------------------
// warp per node; lane = output column (DIM=32). Weights staged in shared.
template <int DIN>
__global__ void gemm_k(const float* __restrict__ X,
                       const float* __restrict__ Wn,
                       const float* __restrict__ Ws,
                       const float* __restrict__ bn,
                       float* __restrict__ H, float* __restrict__ S) {
    __shared__ float wn_s[DIN * 32];
    __shared__ float ws_s[DIN * 32];
    __shared__ float bn_s[32];
    __shared__ float x_s[8][DIN];

    int tid = threadIdx.x;
    for (int i = tid; i < DIN * 32; i += 256) {
        wn_s[i] = Wn[i];
        ws_s[i] = Ws[i];
    }
    if (tid < 32) bn_s[tid] = bn[tid];
    __syncthreads();

    int w = tid >> 5, lane = tid & 31;
    int node = blockIdx.x * 8 + w;
    if (node >= NN) return;

    if (DIN == 128) {
        ((float4*)x_s[w])[lane] = ((const float4*)(X + (size_t)node * DIN))[lane];
    } else {
        x_s[w][lane] = X[(size_t)node * DIN + lane];
    }
    __syncwarp();

    float accn = 0.f, accs = 0.f;
#pragma unroll
    for (int k = 0; k < DIN; k++) {
        float xv = x_s[w][k];
        accn = fmaf(xv, wn_s[k * 32 + lane], accn);
        accs = fmaf(xv, ws_s[k * 32 + lane], accs);
    }
    H[node * 32 + lane] = accn;
    S[node * 32 + lane] = accs + bn_s[lane];
}

// ---------------- aggregation: Out = relu(sum_{e: dst==n} H[src[e]] + S[n]) --
// warp per node; 32 edge indices loaded coalesced, broadcast via shfl;
// 4 accumulators for MLP on the L2 gather.
__global__ void agg_k(const float* __restrict__ H,
                      const float* __restrict__ S,
                      float* __restrict__ Out) {
    int node = (blockIdx.x * blockDim.x + threadIdx.x) >> 5;
    int lane = threadIdx.x & 31;
    if (node >= NN) return;

    int beg = g_rowptr[node], end = g_rowptr[node + 1];
    float a0 = 0.f, a1 = 0.f, a2 = 0.f, a3 = 0.f;
    for (int base = beg; base < end; base += 32) {
        int cnt = end - base;
        if (cnt > 32) cnt = 32;
        int idx = 0;
        if (lane < cnt) idx = g_csrc[base + lane];
        int j = 0;
        for (; j + 4 <= cnt; j += 4) {
            int s0 = __shfl_sync(0xffffffffu, idx, j);
            int s1 = __shfl_sync(0xffffffffu, idx, j + 1);
            int s2 = __shfl_sync(0xffffffffu, idx, j + 2);
            int s3 = __shfl_sync(0xffffffffu, idx, j + 3);
            a0 += H[s0 * 32 + lane];
            a1 += H[s1 * 32 + lane];
            a2 += H[s2 * 32 + lane];
            a3 += H[s3 * 32 + lane];
        }
        for (; j < cnt; j++) {
            int s = __shfl_sync(0xffffffffu, idx, j);
            a0 += H[s * 32 + lane];
        }
    }
    float v = (a0 + a1) + (a2 + a3) + S[node * 32 + lane];
    Out[node * 32 + lane] = fmaxf(v, 0.f);
}

// ---------------- final FC (224 -> 10) + log_softmax -------------------------
// warp per node: lane l covers k = l, l+32, ..., 7 strips. Reduce via shfl_xor.
__global__ void fc_k(const float* __restrict__ X,
                     const float* __restrict__ H1,
                     const float* __restrict__ H2,
                     const float* __restrict__ H3,
                     const float* __restrict__ fcw,
                     const float* __restrict__ fcb,
                     float* __restrict__ out) {
    __shared__ float w_s[224 * 10];
    __shared__ float b_s[10];
    int tid = threadIdx.x;
    for (int i = tid; i < 224 * 10; i += 256) w_s[i] = fcw[i];
    if (tid < 10) b_s[tid] = fcb[tid];
    __syncthreads();

    int w = tid >> 5, lane = tid & 31;
    int node = blockIdx.x * 8 + w;
    if (node >= NN) return;

    float acc[10];
#pragma unroll
    for (int c = 0; c < 10; c++) acc[c] = 0.f;

#pragma unroll
    for (int j = 0; j < 7; j++) {
        float v;
        if (j < 4)        v = X[(size_t)node * 128 + j * 32 + lane];
        else if (j == 4)  v = H1[node * 32 + lane];
        else if (j == 5)  v = H2[node * 32 + lane];
        else              v = H3[node * 32 + lane];
        int k = j * 32 + lane;
#pragma unroll
        for (int c = 0; c < 10; c++) acc[c] = fmaf(v, w_s[k * 10 + c], acc[c]);
    }

    float logit[10];
#pragma unroll
    for (int c = 0; c < 10; c++) {
        float t = acc[c];
#pragma unroll
        for (int off = 16; off; off >>= 1) t += __shfl_xor_sync(0xffffffffu, t, off);
        logit[c] = t + b_s[c];
    }

    float m = logit[0];
#pragma unroll
    for (int c = 1; c < 10; c++) m = fmaxf(m, logit[c]);
    float ssum = 0.f;
#pragma unroll
    for (int c = 0; c < 10; c++) ssum += expf(logit[c] - m);
    float l = logf(ssum);

    float myv = 0.f;
#pragma unroll
    for (int c = 0; c < 10; c++) if (lane == c) myv = logit[c];
    if (lane < 10) out[(size_t)node * 10 + lane] = myv - m - l;
}

// ---------------- launch -----------------------------------------------------
extern "C" void kernel_launch(void* const* d_in, const int* in_sizes, int n_in,
                              void* d_out, int out_size) {
    const float* x   = (const float*)d_in[0];
    const int*   src = (const int*)d_in[1];
    const int*   dst = (const int*)d_in[2];
    const float* Wn0 = (const float*)d_in[3];
    const float* bn0 = (const float*)d_in[4];
    const float* Ws0 = (const float*)d_in[5];
    const float* Wn1 = (const float*)d_in[6];
    const float* bn1 = (const float*)d_in[7];
    const float* Ws1 = (const float*)d_in[8];
    const float* Wn2 = (const float*)d_in[9];
    const float* bn2 = (const float*)d_in[10];
    const float* Ws2 = (const float*)d_in[11];
    const float* fcw = (const float*)d_in[12];
    const float* fcb = (const float*)d_in[13];
    float* out = (float*)d_out;

    void *pH, *pS, *pL;
    cudaGetSymbolAddress(&pH, g_H);
    cudaGetSymbolAddress(&pS, g_S);
    cudaGetSymbolAddress(&pL, g_L);
    float* H  = (float*)pH;
    float* S  = (float*)pS;
    float* L0 = (float*)pL;
    float* L1 = L0 + (size_t)NN * 32;
    float* L2 = L1 + (size_t)NN * 32;

    const int nodeBlocks = (NN + 7) / 8;   // 12500, warp-per-node kernels

    // CSR build (by destination)
    zero_deg_k<<<(NN + 255) / 256, 256>>>();
    count_k<<<(EE + 255) / 256, 256>>>(dst);
    scan_k<<<1, 1024>>>();
    fill_k<<<(EE + 255) / 256, 256>>>(src, dst);

    // Layer 0 (din = 128)
    gemm_k<128><<<nodeBlocks, 256>>>(x, Wn0, Ws0, bn0, H, S);
    agg_k<<<nodeBlocks, 256>>>(H, S, L0);

    // Layer 1 (din = 32)
    gemm_k<32><<<nodeBlocks, 256>>>(L0, Wn1, Ws1, bn1, H, S);
    agg_k<<<nodeBlocks, 256>>>(H, S, L1);

    // Layer 2 (din = 32)
    gemm_k<32><<<nodeBlocks, 256>>>(L1, Wn2, Ws2, bn2, H, S);
    agg_k<<<nodeBlocks, 256>>>(H, S, L2);

    // FC + log_softmax
    fc_k<<<nodeBlocks, 256>>>(x, L0, L1, L2, fcw, fcb, out);
}

// round 4
// speedup vs baseline: 1.3165x; 1.3165x over previous
#include <cuda_runtime.h>
#include <cuda_bf16.h>
#include <cstddef>

#define NN 100000
#define EE 3200000

// ---------------- scratch (static device allocations; no cudaMalloc) ----------
__device__ float g_H[NN * 32];        // neighbor-transformed features (x @ Wn)
__device__ float g_S[NN * 32];        // self part (x @ Ws + bn)
__device__ float g_L[3][NN * 32];     // per-layer outputs (kept for concat)
__device__ int   g_deg[NN];
__device__ int   g_rowptr[NN + 1];
__device__ int   g_rank[EE];          // edge's rank within its dst bucket
__device__ int   g_csrc[EE];          // CSR-by-dst: source node ids

// ---------------- CSR build --------------------------------------------------
__global__ void zero_deg_k() {
    int i = blockIdx.x * blockDim.x + threadIdx.x;
    if (i < NN) g_deg[i] = 0;
}

// count + record per-edge rank (the atomicAdd return we used to throw away)
__global__ void count_k(const int* __restrict__ dst) {
    int e = blockIdx.x * blockDim.x + threadIdx.x;
    if (e < EE) g_rank[e] = atomicAdd(&g_deg[dst[e]], 1);
}

// Single-block exclusive scan over g_deg -> g_rowptr.
__global__ void scan_k() {
    const int T = 1024;
    const int chunk = (NN + T - 1) / T;   // 98
    int t = threadIdx.x;
    int start = t * chunk;
    int end = start + chunk;
    if (end > NN) end = NN;

    int s = 0;
    for (int i = start; i < end; i++) s += g_deg[i];

    __shared__ int sums[T];
    sums[t] = s;
    __syncthreads();
    for (int off = 1; off < T; off <<= 1) {
        int v = (t >= off) ? sums[t - off] : 0;
        __syncthreads();
        sums[t] += v;
        __syncthreads();
    }
    int run = (t == 0) ? 0 : sums[t - 1];
    for (int i = start; i < end; i++) {
        g_rowptr[i] = run;
        run += g_deg[i];
    }
    if (start < NN && end == NN) g_rowptr[NN] = run;
}

// atomic-free fill: p = rowptr[dst] + rank
__global__ void fill_k(const int* __restrict__ src, const int* __restrict__ dst) {
    int e = blockIdx.x * blockDim.x + threadIdx.x;
    if (e < EE) {
        int p = g_rowptr[dst[e]] + g_rank[e];
        g_csrc[p] = src[e];
    }
}

// ---------------- per-layer GEMM: [H | S] = X @ [Wn | Ws] (+bn on S) ---------
// Register-blocked tile GEMM. Block = 256 threads computes 128 nodes x 64 cols.
// Thread computes 8 nodes x 4 cols in registers; x-tile staged transposed.
template <int DIN>
__global__ void __launch_bounds__(256) gemm_k(const float* __restrict__ X,
                       const float* __restrict__ Wn,
                       const float* __restrict__ Ws,
                       const float* __restrict__ bn,
                       float* __restrict__ H, float* __restrict__ S) {
    __shared__ __align__(16) float xs[32][132];   // [k][node], padded
    __shared__ __align__(16) float ws[32][68];    // [k][col 0..63]
    __shared__ __align__(16) float bn_s[32];

    int t = threadIdx.x;
    int base = blockIdx.x * 128;
    if (t < 32) bn_s[t] = bn[t];

    int tm = t & 15, tn = t >> 4;
    int m0 = tm * 8, n0 = tn * 4;

    float acc[8][4];
#pragma unroll
    for (int i = 0; i < 8; i++)
#pragma unroll
        for (int j = 0; j < 4; j++) acc[i][j] = 0.f;

    for (int k0 = 0; k0 < DIN; k0 += 32) {
        __syncthreads();
        // stage weights [32 x 64] = Wn cols 0..31 | Ws cols 32..63
#pragma unroll
        for (int i = t; i < 2048; i += 256) {
            int k = i >> 6, n = i & 63;
            ws[k][n] = (n < 32) ? Wn[(k0 + k) * 32 + n]
                                : Ws[(k0 + k) * 32 + (n - 32)];
        }
        // stage x transposed (float4 global reads, scalar transposed writes)
#pragma unroll
        for (int e = t; e < 1024; e += 256) {
            int node = e >> 3, g = e & 7;
            int gn = base + node;
            float4 v = make_float4(0.f, 0.f, 0.f, 0.f);
            if (gn < NN) v = *(const float4*)(X + (size_t)gn * DIN + k0 + g * 4);
            xs[g * 4 + 0][node] = v.x;
            xs[g * 4 + 1][node] = v.y;
            xs[g * 4 + 2][node] = v.z;
            xs[g * 4 + 3][node] = v.w;
        }
        __syncthreads();
#pragma unroll
        for (int k = 0; k < 32; k++) {
            float4 a0 = *(const float4*)&xs[k][m0];
            float4 a1 = *(const float4*)&xs[k][m0 + 4];
            float4 b  = *(const float4*)&ws[k][n0];
            float av[8] = {a0.x, a0.y, a0.z, a0.w, a1.x, a1.y, a1.z, a1.w};
            float bv[4] = {b.x, b.y, b.z, b.w};
#pragma unroll
            for (int i = 0; i < 8; i++)
#pragma unroll
                for (int j = 0; j < 4; j++)
                    acc[i][j] = fmaf(av[i], bv[j], acc[i][j]);
        }
    }

    bool isS = (n0 >= 32);
    int nc = isS ? (n0 - 32) : n0;
    float4 bias = make_float4(0.f, 0.f, 0.f, 0.f);
    if (isS) bias = *(const float4*)&bn_s[nc];
#pragma unroll
    for (int i = 0; i < 8; i++) {
        int gn = base + m0 + i;
        if (gn < NN) {
            float4 r = make_float4(acc[i][0] + bias.x, acc[i][1] + bias.y,
                                   acc[i][2] + bias.z, acc[i][3] + bias.w);
            float* dstp = isS ? (S + (size_t)gn * 32 + nc)
                              : (H + (size_t)gn * 32 + nc);
            *(float4*)dstp = r;
        }
    }
}

// ---------------- aggregation: Out = relu(sum_{e: dst==n} H[src[e]] + S[n]) --
// warp per node; 32 edge indices loaded coalesced, broadcast via shfl; MLP=8.
__global__ void agg_k(const float* __restrict__ H,
                      const float* __restrict__ S,
                      float* __restrict__ Out) {
    int node = (blockIdx.x * blockDim.x + threadIdx.x) >> 5;
    int lane = threadIdx.x & 31;
    if (node >= NN) return;

    int beg = g_rowptr[node], end = g_rowptr[node + 1];
    float a0 = 0.f, a1 = 0.f, a2 = 0.f, a3 = 0.f;
    float a4 = 0.f, a5 = 0.f, a6 = 0.f, a7 = 0.f;
    for (int base = beg; base < end; base += 32) {
        int cnt = end - base;
        if (cnt > 32) cnt = 32;
        int idx = 0;
        if (lane < cnt) idx = g_csrc[base + lane];
        int j = 0;
        for (; j + 8 <= cnt; j += 8) {
            int s0 = __shfl_sync(0xffffffffu, idx, j);
            int s1 = __shfl_sync(0xffffffffu, idx, j + 1);
            int s2 = __shfl_sync(0xffffffffu, idx, j + 2);
            int s3 = __shfl_sync(0xffffffffu, idx, j + 3);
            int s4 = __shfl_sync(0xffffffffu, idx, j + 4);
            int s5 = __shfl_sync(0xffffffffu, idx, j + 5);
            int s6 = __shfl_sync(0xffffffffu, idx, j + 6);
            int s7 = __shfl_sync(0xffffffffu, idx, j + 7);
            a0 += H[s0 * 32 + lane];
            a1 += H[s1 * 32 + lane];
            a2 += H[s2 * 32 + lane];
            a3 += H[s3 * 32 + lane];
            a4 += H[s4 * 32 + lane];
            a5 += H[s5 * 32 + lane];
            a6 += H[s6 * 32 + lane];
            a7 += H[s7 * 32 + lane];
        }
        for (; j < cnt; j++) {
            int s = __shfl_sync(0xffffffffu, idx, j);
            a0 += H[s * 32 + lane];
        }
    }
    float v = ((a0 + a1) + (a2 + a3)) + ((a4 + a5) + (a6 + a7))
            + S[node * 32 + lane];
    Out[node * 32 + lane] = fmaxf(v, 0.f);
}

// ---------------- final FC (224 -> 10) + log_softmax -------------------------
// thread per node; features staged to shared in 32-wide chunks (coalesced),
// weights broadcast-read as float4 (padded rows of 12) -> no shuffles at all.
__global__ void __launch_bounds__(128) fc_k(const float* __restrict__ X,
                     const float* __restrict__ L0,
                     const float* __restrict__ L1,
                     const float* __restrict__ L2,
                     const float* __restrict__ fcw,
                     const float* __restrict__ fcb,
                     float* __restrict__ out) {
    __shared__ __align__(16) float w_s[224 * 12];  // row k padded to 12 floats
    __shared__ float b_s[12];
    __shared__ float xt[128][33];

    int t = threadIdx.x;
    for (int i = t; i < 224 * 10; i += 128) {
        int k = i / 10, c = i % 10;
        w_s[k * 12 + c] = fcw[i];
    }
    if (t < 10) b_s[t] = fcb[t];

    int node = blockIdx.x * 128 + t;
    float acc[10];
#pragma unroll
    for (int c = 0; c < 10; c++) acc[c] = 0.f;

#pragma unroll
    for (int j = 0; j < 7; j++) {
        __syncthreads();
        const float* srcp;
        int stride;
        if (j < 4)      { srcp = X + j * 32; stride = 128; }
        else if (j == 4){ srcp = L0;         stride = 32;  }
        else if (j == 5){ srcp = L1;         stride = 32;  }
        else            { srcp = L2;         stride = 32;  }
        for (int i = t; i < 128 * 32; i += 128) {
            int nl = i >> 5, k = i & 31;
            int gn = blockIdx.x * 128 + nl;
            xt[nl][k] = (gn < NN) ? srcp[(size_t)gn * stride + k] : 0.f;
        }
        __syncthreads();
#pragma unroll
        for (int kk = 0; kk < 32; kk++) {
            float v = xt[t][kk];
            const float* wr = &w_s[(j * 32 + kk) * 12];
            float4 w0 = *(const float4*)wr;
            float4 w1 = *(const float4*)(wr + 4);
            float2 w2 = *(const float2*)(wr + 8);
            acc[0] = fmaf(v, w0.x, acc[0]);
            acc[1] = fmaf(v, w0.y, acc[1]);
            acc[2] = fmaf(v, w0.z, acc[2]);
            acc[3] = fmaf(v, w0.w, acc[3]);
            acc[4] = fmaf(v, w1.x, acc[4]);
            acc[5] = fmaf(v, w1.y, acc[5]);
            acc[6] = fmaf(v, w1.z, acc[6]);
            acc[7] = fmaf(v, w1.w, acc[7]);
            acc[8] = fmaf(v, w2.x, acc[8]);
            acc[9] = fmaf(v, w2.y, acc[9]);
        }
    }

    float logit[10];
#pragma unroll
    for (int c = 0; c < 10; c++) logit[c] = acc[c] + b_s[c];
    float m = logit[0];
#pragma unroll
    for (int c = 1; c < 10; c++) m = fmaxf(m, logit[c]);
    float ssum = 0.f;
#pragma unroll
    for (int c = 0; c < 10; c++) ssum += expf(logit[c] - m);
    float l = logf(ssum);
    if (node < NN) {
#pragma unroll
        for (int c = 0; c < 10; c++)
            out[(size_t)node * 10 + c] = logit[c] - m - l;
    }
}

// ---------------- launch -----------------------------------------------------
extern "C" void kernel_launch(void* const* d_in, const int* in_sizes, int n_in,
                              void* d_out, int out_size) {
    const float* x   = (const float*)d_in[0];
    const int*   src = (const int*)d_in[1];
    const int*   dst = (const int*)d_in[2];
    const float* Wn0 = (const float*)d_in[3];
    const float* bn0 = (const float*)d_in[4];
    const float* Ws0 = (const float*)d_in[5];
    const float* Wn1 = (const float*)d_in[6];
    const float* bn1 = (const float*)d_in[7];
    const float* Ws1 = (const float*)d_in[8];
    const float* Wn2 = (const float*)d_in[9];
    const float* bn2 = (const float*)d_in[10];
    const float* Ws2 = (const float*)d_in[11];
    const float* fcw = (const float*)d_in[12];
    const float* fcb = (const float*)d_in[13];
    float* out = (float*)d_out;

    void *pH, *pS, *pL;
    cudaGetSymbolAddress(&pH, g_H);
    cudaGetSymbolAddress(&pS, g_S);
    cudaGetSymbolAddress(&pL, g_L);
    float* H  = (float*)pH;
    float* S  = (float*)pS;
    float* L0 = (float*)pL;
    float* L1 = L0 + (size_t)NN * 32;
    float* L2 = L1 + (size_t)NN * 32;

    const int gemmBlocks = (NN + 127) / 128;   // 782
    const int aggBlocks  = (NN + 7) / 8;       // 12500 (warp per node)
    const int fcBlocks   = (NN + 127) / 128;   // 782

    // Fork CSR build onto a side stream to overlap with gemm0.
    // (stream/event creation during capture is legal; intentionally not
    // destroyed while capture may still be active)
    cudaStream_t s2;
    cudaStreamCreateWithFlags(&s2, cudaStreamNonBlocking);
    cudaEvent_t evF, evJ;
    cudaEventCreateWithFlags(&evF, cudaEventDisableTiming);
    cudaEventCreateWithFlags(&evJ, cudaEventDisableTiming);

    cudaEventRecord(evF, 0);
    cudaStreamWaitEvent(s2, evF, 0);

    // CSR chain on s2
    zero_deg_k<<<(NN + 255) / 256, 256, 0, s2>>>();
    count_k<<<(EE + 255) / 256, 256, 0, s2>>>(dst);
    scan_k<<<1, 1024, 0, s2>>>();
    fill_k<<<(EE + 255) / 256, 256, 0, s2>>>(src, dst);
    cudaEventRecord(evJ, s2);

    // gemm0 on main stream, overlapped with CSR build
    gemm_k<128><<<gemmBlocks, 256>>>(x, Wn0, Ws0, bn0, H, S);

    cudaStreamWaitEvent(0, evJ, 0);

    agg_k<<<aggBlocks, 256>>>(H, S, L0);

    gemm_k<32><<<gemmBlocks, 256>>>(L0, Wn1, Ws1, bn1, H, S);
    agg_k<<<aggBlocks, 256>>>(H, S, L1);

    gemm_k<32><<<gemmBlocks, 256>>>(L1, Wn2, Ws2, bn2, H, S);
    agg_k<<<aggBlocks, 256>>>(H, S, L2);

    fc_k<<<fcBlocks, 128>>>(x, L0, L1, L2, fcw, fcb, out);
}

// round 6
// speedup vs baseline: 1.5993x; 1.2148x over previous
#include <cuda_runtime.h>
#include <cuda_bf16.h>
#include <cstddef>

#define NN 100000
#define EE 3200000

// ---------------- scratch (static device allocations; no cudaMalloc) ----------
__device__ float g_H[NN * 32];        // layer0: x @ Wn0
__device__ float g_A[NN * 32];        // layer0: S = x@Ws0+bn0 ; layers 1/2: raw aggregate
__device__ float g_L[3][NN * 32];     // per-layer outputs (kept for concat)
__device__ float g_P[NN * 10];        // partial FC logits (x part + bias)
__device__ int   g_deg[NN];
__device__ int   g_rowptr[NN + 1];
__device__ int   g_rank[EE];          // edge's rank within its dst bucket
__device__ int   g_csrc[EE];          // CSR-by-dst: source node ids

// ---------------- CSR build --------------------------------------------------
// count + record per-edge rank; 4 edges per thread (int4 loads)
__global__ void count_k(const int* __restrict__ dst) {
    int e4 = blockIdx.x * blockDim.x + threadIdx.x;
    if (e4 < EE / 4) {
        int4 d = ((const int4*)dst)[e4];
        int4 r;
        r.x = atomicAdd(&g_deg[d.x], 1);
        r.y = atomicAdd(&g_deg[d.y], 1);
        r.z = atomicAdd(&g_deg[d.z], 1);
        r.w = atomicAdd(&g_deg[d.w], 1);
        ((int4*)g_rank)[e4] = r;
    }
}

// Single-block exclusive scan over g_deg -> g_rowptr.
__global__ void scan_k() {
    const int T = 1024;
    const int chunk = (NN + T - 1) / T;   // 98
    int t = threadIdx.x;
    int start = t * chunk;
    int end = start + chunk;
    if (end > NN) end = NN;

    int s = 0;
    for (int i = start; i < end; i++) s += g_deg[i];

    __shared__ int sums[T];
    sums[t] = s;
    __syncthreads();
    for (int off = 1; off < T; off <<= 1) {
        int v = (t >= off) ? sums[t - off] : 0;
        __syncthreads();
        sums[t] += v;
        __syncthreads();
    }
    int run = (t == 0) ? 0 : sums[t - 1];
    for (int i = start; i < end; i++) {
        g_rowptr[i] = run;
        run += g_deg[i];
    }
    if (start < NN && end == NN) g_rowptr[NN] = run;
}

// atomic-free fill: p = rowptr[dst] + rank; 4 edges per thread
__global__ void fill_k(const int* __restrict__ src, const int* __restrict__ dst) {
    int e4 = blockIdx.x * blockDim.x + threadIdx.x;
    if (e4 < EE / 4) {
        int4 s = ((const int4*)src)[e4];
        int4 d = ((const int4*)dst)[e4];
        int4 r = ((const int4*)g_rank)[e4];
        g_csrc[g_rowptr[d.x] + r.x] = s.x;
        g_csrc[g_rowptr[d.y] + r.y] = s.y;
        g_csrc[g_rowptr[d.z] + r.z] = s.z;
        g_csrc[g_rowptr[d.w] + r.w] = s.w;
    }
}

// ---------------- layer0 GEMM: [H | S] = X @ [Wn | Ws] (+bn on S) ------------
// Register-blocked tile GEMM. Block = 256 threads computes 128 nodes x 64 cols.
__global__ void __launch_bounds__(256) gemm0_k(const float* __restrict__ X,
                       const float* __restrict__ Wn,
                       const float* __restrict__ Ws,
                       const float* __restrict__ bn,
                       float* __restrict__ H, float* __restrict__ S) {
    __shared__ __align__(16) float xs[32][132];   // [k][node], padded
    __shared__ __align__(16) float ws[32][68];    // [k][col 0..63]
    __shared__ __align__(16) float bn_s[32];

    int t = threadIdx.x;
    int base = blockIdx.x * 128;
    if (t < 32) bn_s[t] = bn[t];

    int tm = t & 15, tn = t >> 4;
    int m0 = tm * 8, n0 = tn * 4;

    float acc[8][4];
#pragma unroll
    for (int i = 0; i < 8; i++)
#pragma unroll
        for (int j = 0; j < 4; j++) acc[i][j] = 0.f;

    for (int k0 = 0; k0 < 128; k0 += 32) {
        __syncthreads();
#pragma unroll
        for (int i = t; i < 2048; i += 256) {
            int k = i >> 6, n = i & 63;
            ws[k][n] = (n < 32) ? Wn[(k0 + k) * 32 + n]
                                : Ws[(k0 + k) * 32 + (n - 32)];
        }
#pragma unroll
        for (int e = t; e < 1024; e += 256) {
            int node = e >> 3, g = e & 7;
            int gn = base + node;
            float4 v = make_float4(0.f, 0.f, 0.f, 0.f);
            if (gn < NN) v = *(const float4*)(X + (size_t)gn * 128 + k0 + g * 4);
            xs[g * 4 + 0][node] = v.x;
            xs[g * 4 + 1][node] = v.y;
            xs[g * 4 + 2][node] = v.z;
            xs[g * 4 + 3][node] = v.w;
        }
        __syncthreads();
#pragma unroll
        for (int k = 0; k < 32; k++) {
            float4 a0 = *(const float4*)&xs[k][m0];
            float4 a1 = *(const float4*)&xs[k][m0 + 4];
            float4 b  = *(const float4*)&ws[k][n0];
            float av[8] = {a0.x, a0.y, a0.z, a0.w, a1.x, a1.y, a1.z, a1.w};
            float bv[4] = {b.x, b.y, b.z, b.w};
#pragma unroll
            for (int i = 0; i < 8; i++)
#pragma unroll
                for (int j = 0; j < 4; j++)
                    acc[i][j] = fmaf(av[i], bv[j], acc[i][j]);
        }
    }

    bool isS = (n0 >= 32);
    int nc = isS ? (n0 - 32) : n0;
    float4 bias = make_float4(0.f, 0.f, 0.f, 0.f);
    if (isS) bias = *(const float4*)&bn_s[nc];
#pragma unroll
    for (int i = 0; i < 8; i++) {
        int gn = base + m0 + i;
        if (gn < NN) {
            float4 r = make_float4(acc[i][0] + bias.x, acc[i][1] + bias.y,
                                   acc[i][2] + bias.z, acc[i][3] + bias.w);
            float* dstp = isS ? (S + (size_t)gn * 32 + nc)
                              : (H + (size_t)gn * 32 + nc);
            *(float4*)dstp = r;
        }
    }
}

// ---------------- vectorized aggregation -------------------------------------
// Warp per node; lane = slot*8 + pos. One LDG.128 covers 4 edges' float4 chunks.
// ADD_S_RELU: Out = relu(gathersum + S)  ; else Out = gathersum (raw)
template <bool ADD_S_RELU>
__global__ void agg_k(const float* __restrict__ G,
                      const float* __restrict__ S,
                      float* __restrict__ Out) {
    int node = (blockIdx.x * blockDim.x + threadIdx.x) >> 5;
    int lane = threadIdx.x & 31;
    if (node >= NN) return;
    int s = lane >> 3, p = lane & 7;

    const float4* G4 = (const float4*)G;
    int beg = g_rowptr[node], end = g_rowptr[node + 1];

    float4 accA = make_float4(0.f, 0.f, 0.f, 0.f);
    float4 accB = make_float4(0.f, 0.f, 0.f, 0.f);

    for (int base = beg; base < end; base += 32) {
        int cnt = end - base;
        if (cnt > 32) cnt = 32;
        int idx = 0;
        if (lane < cnt) idx = g_csrc[base + lane];
#pragma unroll 4
        for (int j = 0; j < cnt; j += 8) {
            int e0 = __shfl_sync(0xffffffffu, idx, j + s);
            int e1 = __shfl_sync(0xffffffffu, idx, j + 4 + s);
            if (j + s < cnt) {
                float4 v = G4[e0 * 8 + p];
                accA.x += v.x; accA.y += v.y; accA.z += v.z; accA.w += v.w;
            }
            if (j + 4 + s < cnt) {
                float4 v = G4[e1 * 8 + p];
                accB.x += v.x; accB.y += v.y; accB.z += v.z; accB.w += v.w;
            }
        }
    }

    float4 v = make_float4(accA.x + accB.x, accA.y + accB.y,
                           accA.z + accB.z, accA.w + accB.w);
    // reduce across the 4 edge slots (lanes xor 8, 16)
    v.x += __shfl_xor_sync(0xffffffffu, v.x, 8);
    v.y += __shfl_xor_sync(0xffffffffu, v.y, 8);
    v.z += __shfl_xor_sync(0xffffffffu, v.z, 8);
    v.w += __shfl_xor_sync(0xffffffffu, v.w, 8);
    v.x += __shfl_xor_sync(0xffffffffu, v.x, 16);
    v.y += __shfl_xor_sync(0xffffffffu, v.y, 16);
    v.z += __shfl_xor_sync(0xffffffffu, v.z, 16);
    v.w += __shfl_xor_sync(0xffffffffu, v.w, 16);

    if (s == 0) {
        if (ADD_S_RELU) {
            float4 sv = ((const float4*)S)[node * 8 + p];
            v.x = fmaxf(v.x + sv.x, 0.f);
            v.y = fmaxf(v.y + sv.y, 0.f);
            v.z = fmaxf(v.z + sv.z, 0.f);
            v.w = fmaxf(v.w + sv.w, 0.f);
        }
        ((float4*)Out)[node * 8 + p] = v;
    }
}

// ---------------- fused layer GEMM (layers 1,2): out = relu(A@Wn + X@Ws + bn)
// Equivalent to [A|X] @ vstack(Wn,Ws), K=64. Block: 256 thr = 128 nodes x 32 cols.
__global__ void __launch_bounds__(256) fgemm_k(const float* __restrict__ A,
                       const float* __restrict__ X,
                       const float* __restrict__ Wn,
                       const float* __restrict__ Ws,
                       const float* __restrict__ bn,
                       float* __restrict__ Out) {
    __shared__ __align__(16) float xs[64][132];   // [k][node]; k<32: A, k>=32: X
    __shared__ __align__(16) float ws[64][36];    // [k][col]
    __shared__ __align__(16) float bn_s[32];

    int t = threadIdx.x;
    int base = blockIdx.x * 128;
    if (t < 32) bn_s[t] = bn[t];

#pragma unroll
    for (int i = t; i < 2048; i += 256) {
        int k = i >> 5, n = i & 31;
        ws[k][n] = (k < 32) ? Wn[k * 32 + n] : Ws[(k - 32) * 32 + n];
    }
    const float4* A4 = (const float4*)A;
    const float4* X4 = (const float4*)X;
#pragma unroll
    for (int e = t; e < 2048; e += 256) {
        int node = e >> 4, g = e & 15;
        int gn = base + node;
        float4 v = make_float4(0.f, 0.f, 0.f, 0.f);
        if (gn < NN) v = (g < 8) ? A4[gn * 8 + g] : X4[gn * 8 + (g - 8)];
        int k = g * 4;
        xs[k + 0][node] = v.x;
        xs[k + 1][node] = v.y;
        xs[k + 2][node] = v.z;
        xs[k + 3][node] = v.w;
    }
    __syncthreads();

    int tm = t & 31, tn = t >> 5;   // 32 x 8
    int m0 = tm * 4, n0 = tn * 4;

    float acc[4][4];
#pragma unroll
    for (int i = 0; i < 4; i++)
#pragma unroll
        for (int j = 0; j < 4; j++) acc[i][j] = 0.f;

#pragma unroll
    for (int k = 0; k < 64; k++) {
        float4 a = *(const float4*)&xs[k][m0];
        float4 b = *(const float4*)&ws[k][n0];
        float av[4] = {a.x, a.y, a.z, a.w};
        float bv[4] = {b.x, b.y, b.z, b.w};
#pragma unroll
        for (int i = 0; i < 4; i++)
#pragma unroll
            for (int j = 0; j < 4; j++)
                acc[i][j] = fmaf(av[i], bv[j], acc[i][j]);
    }

    float4 bias = *(const float4*)&bn_s[n0];
#pragma unroll
    for (int i = 0; i < 4; i++) {
        int gn = base + m0 + i;
        if (gn < NN) {
            float4 r;
            r.x = fmaxf(acc[i][0] + bias.x, 0.f);
            r.y = fmaxf(acc[i][1] + bias.y, 0.f);
            r.z = fmaxf(acc[i][2] + bias.z, 0.f);
            r.w = fmaxf(acc[i][3] + bias.w, 0.f);
            *(float4*)(Out + (size_t)gn * 32 + n0) = r;
        }
    }
}

// ---------------- FC phase 1: partial logits from x (k = 0..127) + bias ------
__global__ void __launch_bounds__(128) fc1_k(const float* __restrict__ X,
                     const float* __restrict__ fcw,
                     const float* __restrict__ fcb,
                     float* __restrict__ partial) {
    __shared__ __align__(16) float w_s[128 * 12];
    __shared__ float b_s[12];
    __shared__ float xt[128][33];

    int t = threadIdx.x;
    for (int i = t; i < 128 * 10; i += 128) {
        int k = i / 10, c = i % 10;
        w_s[k * 12 + c] = fcw[k * 10 + c];
    }
    if (t < 10) b_s[t] = fcb[t];

    int node = blockIdx.x * 128 + t;
    float acc[10];
#pragma unroll
    for (int c = 0; c < 10; c++) acc[c] = 0.f;

#pragma unroll
    for (int j = 0; j < 4; j++) {
        __syncthreads();
        for (int i = t; i < 128 * 32; i += 128) {
            int nl = i >> 5, k = i & 31;
            int gn = blockIdx.x * 128 + nl;
            xt[nl][k] = (gn < NN) ? X[(size_t)gn * 128 + j * 32 + k] : 0.f;
        }
        __syncthreads();
#pragma unroll
        for (int kk = 0; kk < 32; kk++) {
            float v = xt[t][kk];
            const float* wr = &w_s[(j * 32 + kk) * 12];
            float4 w0 = *(const float4*)wr;
            float4 w1 = *(const float4*)(wr + 4);
            float2 w2 = *(const float2*)(wr + 8);
            acc[0] = fmaf(v, w0.x, acc[0]);
            acc[1] = fmaf(v, w0.y, acc[1]);
            acc[2] = fmaf(v, w0.z, acc[2]);
            acc[3] = fmaf(v, w0.w, acc[3]);
            acc[4] = fmaf(v, w1.x, acc[4]);
            acc[5] = fmaf(v, w1.y, acc[5]);
            acc[6] = fmaf(v, w1.z, acc[6]);
            acc[7] = fmaf(v, w1.w, acc[7]);
            acc[8] = fmaf(v, w2.x, acc[8]);
            acc[9] = fmaf(v, w2.y, acc[9]);
        }
    }
    if (node < NN) {
#pragma unroll
        for (int c = 0; c < 10; c++)
            partial[(size_t)node * 10 + c] = acc[c] + b_s[c];
    }
}

// ---------------- FC phase 2: L parts (k = 128..223) + log_softmax -----------
__global__ void __launch_bounds__(128) fc2_k(const float* __restrict__ L0,
                     const float* __restrict__ L1,
                     const float* __restrict__ L2,
                     const float* __restrict__ fcw,
                     const float* __restrict__ partial,
                     float* __restrict__ out) {
    __shared__ __align__(16) float w_s[96 * 12];
    __shared__ float xt[128][33];

    int t = threadIdx.x;
    for (int i = t; i < 96 * 10; i += 128) {
        int k = i / 10, c = i % 10;
        w_s[k * 12 + c] = fcw[(128 + k) * 10 + c];
    }

    int node = blockIdx.x * 128 + t;
    float acc[10];
#pragma unroll
    for (int c = 0; c < 10; c++) acc[c] = 0.f;

#pragma unroll
    for (int j = 0; j < 3; j++) {
        __syncthreads();
        const float* srcp = (j == 0) ? L0 : (j == 1) ? L1 : L2;
        for (int i = t; i < 128 * 32; i += 128) {
            int nl = i >> 5, k = i & 31;
            int gn = blockIdx.x * 128 + nl;
            xt[nl][k] = (gn < NN) ? srcp[(size_t)gn * 32 + k] : 0.f;
        }
        __syncthreads();
#pragma unroll
        for (int kk = 0; kk < 32; kk++) {
            float v = xt[t][kk];
            const float* wr = &w_s[(j * 32 + kk) * 12];
            float4 w0 = *(const float4*)wr;
            float4 w1 = *(const float4*)(wr + 4);
            float2 w2 = *(const float2*)(wr + 8);
            acc[0] = fmaf(v, w0.x, acc[0]);
            acc[1] = fmaf(v, w0.y, acc[1]);
            acc[2] = fmaf(v, w0.z, acc[2]);
            acc[3] = fmaf(v, w0.w, acc[3]);
            acc[4] = fmaf(v, w1.x, acc[4]);
            acc[5] = fmaf(v, w1.y, acc[5]);
            acc[6] = fmaf(v, w1.z, acc[6]);
            acc[7] = fmaf(v, w1.w, acc[7]);
            acc[8] = fmaf(v, w2.x, acc[8]);
            acc[9] = fmaf(v, w2.y, acc[9]);
        }
    }

    if (node < NN) {
        float logit[10];
#pragma unroll
        for (int c = 0; c < 10; c++)
            logit[c] = acc[c] + partial[(size_t)node * 10 + c];
        float m = logit[0];
#pragma unroll
        for (int c = 1; c < 10; c++) m = fmaxf(m, logit[c]);
        float ssum = 0.f;
#pragma unroll
        for (int c = 0; c < 10; c++) ssum += expf(logit[c] - m);
        float l = logf(ssum);
#pragma unroll
        for (int c = 0; c < 10; c++)
            out[(size_t)node * 10 + c] = logit[c] - m - l;
    }
}

// ---------------- launch -----------------------------------------------------
extern "C" void kernel_launch(void* const* d_in, const int* in_sizes, int n_in,
                              void* d_out, int out_size) {
    const float* x   = (const float*)d_in[0];
    const int*   src = (const int*)d_in[1];
    const int*   dst = (const int*)d_in[2];
    const float* Wn0 = (const float*)d_in[3];
    const float* bn0 = (const float*)d_in[4];
    const float* Ws0 = (const float*)d_in[5];
    const float* Wn1 = (const float*)d_in[6];
    const float* bn1 = (const float*)d_in[7];
    const float* Ws1 = (const float*)d_in[8];
    const float* Wn2 = (const float*)d_in[9];
    const float* bn2 = (const float*)d_in[10];
    const float* Ws2 = (const float*)d_in[11];
    const float* fcw = (const float*)d_in[12];
    const float* fcb = (const float*)d_in[13];
    float* out = (float*)d_out;

    void *pH, *pA, *pL, *pP, *pDeg;
    cudaGetSymbolAddress(&pH, g_H);
    cudaGetSymbolAddress(&pA, g_A);
    cudaGetSymbolAddress(&pL, g_L);
    cudaGetSymbolAddress(&pP, g_P);
    cudaGetSymbolAddress(&pDeg, g_deg);
    float* H  = (float*)pH;
    float* A  = (float*)pA;
    float* L0 = (float*)pL;
    float* L1 = L0 + (size_t)NN * 32;
    float* L2 = L1 + (size_t)NN * 32;
    float* P  = (float*)pP;

    const int gemmBlocks = (NN + 127) / 128;   // 782
    const int aggBlocks  = (NN + 7) / 8;       // 12500 (warp per node)
    const int fcBlocks   = (NN + 127) / 128;   // 782

    // Fork CSR build onto a side stream, overlapped with gemm0 + fc1.
    cudaStream_t s2;
    cudaStreamCreateWithFlags(&s2, cudaStreamNonBlocking);
    cudaEvent_t evF, evJ;
    cudaEventCreateWithFlags(&evF, cudaEventDisableTiming);
    cudaEventCreateWithFlags(&evJ, cudaEventDisableTiming);

    cudaEventRecord(evF, 0);
    cudaStreamWaitEvent(s2, evF, 0);

    // CSR chain on s2
    cudaMemsetAsync(pDeg, 0, NN * sizeof(int), s2);
    count_k<<<(EE / 4 + 255) / 256, 256, 0, s2>>>(dst);
    scan_k<<<1, 1024, 0, s2>>>();
    fill_k<<<(EE / 4 + 255) / 256, 256, 0, s2>>>(src, dst);
    cudaEventRecord(evJ, s2);

    // main stream: gemm0 (H = x@Wn0, A = x@Ws0+bn0) and FC x-part, overlapped
    gemm0_k<<<gemmBlocks, 256>>>(x, Wn0, Ws0, bn0, H, A);
    fc1_k<<<fcBlocks, 128>>>(x, fcw, fcb, P);

    cudaStreamWaitEvent(0, evJ, 0);

    // layer 0: L0 = relu(segsum(H[src]) + S)
    agg_k<true><<<aggBlocks, 256>>>(H, A, L0);

    // layer 1: A = segsum(L0[src]);  L1 = relu(A@Wn1 + L0@Ws1 + bn1)
    agg_k<false><<<aggBlocks, 256>>>(L0, nullptr, A);
    fgemm_k<<<gemmBlocks, 256>>>(A, L0, Wn1, Ws1, bn1, L1);

    // layer 2
    agg_k<false><<<aggBlocks, 256>>>(L1, nullptr, A);
    fgemm_k<<<gemmBlocks, 256>>>(A, L1, Wn2, Ws2, bn2, L2);

    // FC phase 2 + log_softmax
    fc2_k<<<fcBlocks, 128>>>(L0, L1, L2, fcw, P, out);
}